// round 14
// baseline (speedup 1.0000x reference)
#include <cuda_runtime.h>
#include <cuda_bf16.h>
#include <cuda_fp16.h>
#include <cuda_fp8.h>
#include <cstdint>
#include <cstddef>

#define C_ 100
#define B_ 512
#define E_ 2048
#define F_ 128

#define NKT 32                 // k-tiles of 64
#define STAGE_BYTES 65536      // XH16,WH16 (16KB ea) + XH8,XL8,WH8,WL8 (8KB ea)
#define DSMEM_SIZE (3 * STAGE_BYTES)

// stage offsets
#define OFF_XH16 0u
#define OFF_WH16 16384u
#define OFF_XH8  32768u
#define OFF_XL8  40960u
#define OFF_WH8  49152u
#define OFF_WL8  57344u

// ---------------- device scratch ----------------
__device__ __align__(1024) __half  g_xh16[B_ * E_];
__device__ __align__(1024) uint8_t g_xh8[B_ * E_];
__device__ __align__(1024) uint8_t g_xl8[B_ * E_];
__device__ __align__(1024) __half  g_wh16[(size_t)C_ * F_ * E_];
__device__ __align__(1024) uint8_t g_wh8[(size_t)C_ * F_ * E_];
__device__ __align__(1024) uint8_t g_wl8[(size_t)C_ * F_ * E_];
__device__ float g_vraw[C_ * E_];
__device__ float g_nrm2p[C_ * 2];
__device__ float g_s2p[C_ * 64];

// ---------------- helpers ----------------
__device__ __forceinline__ uint32_t smem_u32(const void* p) {
    uint32_t a;
    asm("{ .reg .u64 t; cvta.to.shared.u64 t, %1; cvt.u32.u64 %0, t; }" : "=r"(a) : "l"(p));
    return a;
}
__device__ __forceinline__ void cp16(uint32_t dst, const void* src) {
    asm volatile("cp.async.cg.shared.global [%0], [%1], 16;" :: "r"(dst), "l"(src) : "memory");
}
__device__ __forceinline__ unsigned short pk8(float a, float b) {
    return __nv_cvt_float2_to_fp8x2(make_float2(a, b), __NV_SATFINITE, __NV_E4M3);
}

// =====================================================================
// split x:  xh = f32(fp16(x)), xl = x - xh
//   g_xh16 = fp16(xh*128), g_xh8 = e4m3(xh), g_xl8 = e4m3(xl*2048)
// =====================================================================
__global__ void split_x_kernel(const float* __restrict__ x) {
    int i = (blockIdx.x * 256 + threadIdx.x) * 2;
    float2 v = *(const float2*)&x[i];
    __half h0 = __float2half(v.x), h1 = __float2half(v.y);
    float xh0 = __half2float(h0), xh1 = __half2float(h1);
    float xl0 = v.x - xh0, xl1 = v.y - xh1;
    __half2 h16 = __halves2half2(__float2half(xh0 * 128.f), __float2half(xh1 * 128.f));
    *(__half2*)&g_xh16[i] = h16;
    *(unsigned short*)&g_xh8[i] = pk8(xh0, xh1);
    *(unsigned short*)&g_xl8[i] = pk8(xl0 * 2048.f, xl1 * 2048.f);
}

// =====================================================================
// fused: W split (fp16 + fp8 corr operands) AND v_raw = W^T u
//   g_wh16 = fp16(wh*256), g_wh8 = e4m3(wh*16), g_wl8 = e4m3(wl*32768)
// grid (C, 2), 256 threads; block owns e-range of 1024 (4 e per thread)
// =====================================================================
__global__ void wsplit_v_kernel(const float* __restrict__ W, const float* __restrict__ u) {
    int c = blockIdx.x, et = blockIdx.y;
    __shared__ float su[F_];
    __shared__ float red[8];
    int tid = threadIdx.x, lane = tid & 31, wrp = tid >> 5;

    if (tid < F_) su[tid] = u[c * F_ + tid];
    __syncthreads();

    int e0 = et * 1024 + tid * 4;
    const float* base = W + (size_t)c * F_ * E_ + e0;
    float v0 = 0.f, v1 = 0.f, v2 = 0.f, v3 = 0.f;
    #pragma unroll 8
    for (int f = 0; f < F_; f++) {
        float4 w = *(const float4*)(base + (size_t)f * E_);
        float uf = su[f];
        v0 = fmaf(w.x, uf, v0);
        v1 = fmaf(w.y, uf, v1);
        v2 = fmaf(w.z, uf, v2);
        v3 = fmaf(w.w, uf, v3);
        __half h0 = __float2half(w.x), h1 = __float2half(w.y);
        __half h2 = __float2half(w.z), h3 = __float2half(w.w);
        float wh0 = __half2float(h0), wh1 = __half2float(h1);
        float wh2 = __half2float(h2), wh3 = __half2float(h3);
        float wl0 = w.x - wh0, wl1 = w.y - wh1;
        float wl2 = w.z - wh2, wl3 = w.w - wh3;
        size_t oi = (size_t)(c * F_ + f) * E_ + e0;
        *(__half2*)&g_wh16[oi]     = __halves2half2(__float2half(wh0 * 256.f), __float2half(wh1 * 256.f));
        *(__half2*)&g_wh16[oi + 2] = __halves2half2(__float2half(wh2 * 256.f), __float2half(wh3 * 256.f));
        *(unsigned short*)&g_wh8[oi]     = pk8(wh0 * 16.f, wh1 * 16.f);
        *(unsigned short*)&g_wh8[oi + 2] = pk8(wh2 * 16.f, wh3 * 16.f);
        *(unsigned short*)&g_wl8[oi]     = pk8(wl0 * 32768.f, wl1 * 32768.f);
        *(unsigned short*)&g_wl8[oi + 2] = pk8(wl2 * 32768.f, wl3 * 32768.f);
    }
    *(float4*)&g_vraw[c * E_ + e0] = make_float4(v0, v1, v2, v3);

    float loc = v0 * v0 + v1 * v1 + v2 * v2 + v3 * v3;
    #pragma unroll
    for (int o = 16; o; o >>= 1) loc += __shfl_xor_sync(0xffffffffu, loc, o);
    if (lane == 0) red[wrp] = loc;
    __syncthreads();
    if (tid == 0) {
        float s = 0.f;
        #pragma unroll
        for (int i = 0; i < 8; i++) s += red[i];
        g_nrm2p[c * 2 + et] = s;
    }
}

// =====================================================================
// t = W v_hat; partial sum of t^2. grid (C, 8), 256 threads. (exact fp32)
// =====================================================================
__global__ void wv_kernel(const float* __restrict__ W) {
    int c = blockIdx.x, ft = blockIdx.y;
    __shared__ float sv[E_];
    __shared__ float s_inv;
    int tid = threadIdx.x, lane = tid & 31, wrp = tid >> 5;

    if (tid == 0)
        s_inv = 1.f / fmaxf(sqrtf(g_nrm2p[c * 2] + g_nrm2p[c * 2 + 1]), 1e-12f);
    __syncthreads();
    float inv = s_inv;
    for (int i = tid * 4; i < E_; i += 1024) {
        float4 v = *(const float4*)&g_vraw[c * E_ + i];
        v.x *= inv; v.y *= inv; v.z *= inv; v.w *= inv;
        *(float4*)&sv[i] = v;
    }
    __syncthreads();

    int f0 = ft * 16 + wrp * 2;
    const float* p0 = W + ((size_t)c * F_ + f0) * E_;
    const float* p1 = p0 + E_;
    float t0 = 0.f, t1 = 0.f;
    #pragma unroll 8
    for (int e = lane * 4; e < E_; e += 128) {
        float4 a = *(const float4*)(p0 + e);
        float4 b = *(const float4*)(p1 + e);
        float4 v = *(const float4*)&sv[e];
        t0 = fmaf(a.x, v.x, t0); t0 = fmaf(a.y, v.y, t0);
        t0 = fmaf(a.z, v.z, t0); t0 = fmaf(a.w, v.w, t0);
        t1 = fmaf(b.x, v.x, t1); t1 = fmaf(b.y, v.y, t1);
        t1 = fmaf(b.z, v.z, t1); t1 = fmaf(b.w, v.w, t1);
    }
    #pragma unroll
    for (int o = 16; o; o >>= 1) {
        t0 += __shfl_xor_sync(0xffffffffu, t0, o);
        t1 += __shfl_xor_sync(0xffffffffu, t1, o);
    }
    if (lane == 0) g_s2p[c * 64 + ft * 8 + wrp] = t0 * t0 + t1 * t1;
}

// =====================================================================
// Main kernel: BM=128, BN=128, BK=64, 3x64KB stages, grid (4, C_).
//   acc (scale 2^15) = (xh*2^7)(wh*2^8)  [fp16 m16n8k16]
//                    + (xh)(wl*2^15) + (xl*2^11)(wh*2^4)  [e4m3 m16n8k32]
//   out = exp(-0.5 * sum_f (cent - (acc*inv_s/2^15 + bias))^2)
// =====================================================================
__global__ void __launch_bounds__(256, 1)
mm_kernel(const float* __restrict__ bias, const float* __restrict__ cent,
          float* __restrict__ out)
{
    extern __shared__ __align__(1024) char dsm[];
    __shared__ float s_bias[F_], s_cent[F_];
    __shared__ float part[128][4];
    __shared__ float s_invs;

    int bt = blockIdx.x, c = blockIdx.y;
    int tid = threadIdx.x, wid = tid >> 5, lane = tid & 31;

    if (tid < F_) {
        s_bias[tid] = bias[c * F_ + tid];
        s_cent[tid] = cent[c * F_ + tid];
    }
    if (wid == 0) {
        float s = g_s2p[c * 64 + lane] + g_s2p[c * 64 + 32 + lane];
        #pragma unroll
        for (int o = 16; o; o >>= 1) s += __shfl_xor_sync(0xffffffffu, s, o);
        if (lane == 0) s_invs = 1.f / sqrtf(s);
    }

    uint32_t dbase = smem_u32(dsm);
    int warp_m = wid >> 2, warp_n = wid & 3;

    float acc[4][4][4];
    #pragma unroll
    for (int mt = 0; mt < 4; mt++)
        #pragma unroll
        for (int nt = 0; nt < 4; nt++)
            #pragma unroll
            for (int q = 0; q < 4; q++) acc[mt][nt][q] = 0.f;

    // ---- cp.async mappings ----
    // fp16 tiles (128 rows x 128B): r0 = tid>>3 (+32j), kc = tid&7
    int r0 = tid >> 3, kc = tid & 7;
    uint32_t drow16 = (uint32_t)r0 * 128u + (uint32_t)((kc ^ (r0 & 7)) << 4);
    // fp8 tiles (128 rows x 64B): r8 = tid>>1, cb0 = (tid&1)*2 (+j)
    int r8 = tid >> 1, cb0 = (tid & 1) * 2;
    uint32_t dsw8_0 = (uint32_t)r8 * 64u + (uint32_t)(((cb0 + 0) ^ ((r8 >> 1) & 3)) << 4);
    uint32_t dsw8_1 = (uint32_t)r8 * 64u + (uint32_t)(((cb0 + 1) ^ ((r8 >> 1) & 3)) << 4);

    const __half*   xh16_s = g_xh16 + (size_t)(bt * 128 + r0) * E_ + kc * 8;
    const __half*   wh16_s = g_wh16 + (size_t)(c * 128 + r0) * E_ + kc * 8;
    const uint8_t*  xh8_s  = g_xh8  + (size_t)(bt * 128 + r8) * E_ + cb0 * 16;
    const uint8_t*  xl8_s  = g_xl8  + (size_t)(bt * 128 + r8) * E_ + cb0 * 16;
    const uint8_t*  wh8_s  = g_wh8  + (size_t)(c * 128 + r8) * E_ + cb0 * 16;
    const uint8_t*  wl8_s  = g_wl8  + (size_t)(c * 128 + r8) * E_ + cb0 * 16;

    // fragment addressing
    int matB = lane >> 3, rrB = lane & 7;
    int rowB0 = warp_n * 32 + ((matB >> 1) << 3) + rrB;
    int rowB1 = rowB0 + 16;
    int rowmA = warp_m * 64 + ((lane >> 3) & 1) * 8 + (lane & 7);

#define STAGE_ADDR(s) (dbase + (uint32_t)(s) * (uint32_t)STAGE_BYTES)
#define LOAD_STAGE(slot, kt) do { \
    uint32_t _sa = STAGE_ADDR(slot); \
    int _k16 = (kt) << 6;            /* half offset   */ \
    int _k8  = (kt) << 6;            /* byte offset   */ \
    _Pragma("unroll") \
    for (int _j = 0; _j < 4; _j++) { \
        cp16(_sa + OFF_XH16 + drow16 + _j * 4096u, xh16_s + _k16 + (size_t)_j * 32 * E_); \
        cp16(_sa + OFF_WH16 + drow16 + _j * 4096u, wh16_s + _k16 + (size_t)_j * 32 * E_); \
    } \
    cp16(_sa + OFF_XH8 + dsw8_0, xh8_s + _k8); \
    cp16(_sa + OFF_XH8 + dsw8_1, xh8_s + _k8 + 16); \
    cp16(_sa + OFF_XL8 + dsw8_0, xl8_s + _k8); \
    cp16(_sa + OFF_XL8 + dsw8_1, xl8_s + _k8 + 16); \
    cp16(_sa + OFF_WH8 + dsw8_0, wh8_s + _k8); \
    cp16(_sa + OFF_WH8 + dsw8_1, wh8_s + _k8 + 16); \
    cp16(_sa + OFF_WL8 + dsw8_0, wl8_s + _k8); \
    cp16(_sa + OFF_WL8 + dsw8_1, wl8_s + _k8 + 16); \
    asm volatile("cp.async.commit_group;" ::: "memory"); \
} while (0)

#define MMA16(d, a, b) \
    asm volatile("mma.sync.aligned.m16n8k16.row.col.f32.f16.f16.f32 " \
                 "{%0,%1,%2,%3}, {%4,%5,%6,%7}, {%8,%9}, {%0,%1,%2,%3};" \
                 : "+f"((d)[0]), "+f"((d)[1]), "+f"((d)[2]), "+f"((d)[3]) \
                 : "r"((a)[0]), "r"((a)[1]), "r"((a)[2]), "r"((a)[3]), \
                   "r"((b)[0]), "r"((b)[1]))
#define MMA8(d, a, b) \
    asm volatile("mma.sync.aligned.m16n8k32.row.col.f32.e4m3.e4m3.f32 " \
                 "{%0,%1,%2,%3}, {%4,%5,%6,%7}, {%8,%9}, {%0,%1,%2,%3};" \
                 : "+f"((d)[0]), "+f"((d)[1]), "+f"((d)[2]), "+f"((d)[3]) \
                 : "r"((a)[0]), "r"((a)[1]), "r"((a)[2]), "r"((a)[3]), \
                   "r"((b)[0]), "r"((b)[1]))

    LOAD_STAGE(0, 0);
    LOAD_STAGE(1, 1);

    for (int it = 0; it < NKT; it++) {
        int s = it % 3;
        if (it == NKT - 1) asm volatile("cp.async.wait_group 0;" ::: "memory");
        else               asm volatile("cp.async.wait_group 1;" ::: "memory");
        __syncthreads();
        if (it + 2 < NKT) LOAD_STAGE((it + 2) % 3, it + 2);

        uint32_t sa = STAGE_ADDR(s);
        uint32_t XH16 = sa + OFF_XH16, WH16 = sa + OFF_WH16;
        uint32_t XH8 = sa + OFF_XH8, XL8 = sa + OFF_XL8;
        uint32_t WH8 = sa + OFF_WH8, WL8 = sa + OFF_WL8;

        // ---------- fp16 main: (xh*2^7)(wh*2^8), 4 k16-chunks ----------
        #pragma unroll
        for (int kk = 0; kk < 4; kk++) {
            uint32_t bh[4][2];
            int kcb = kk * 2 + (matB & 1);
            {
                uint32_t o0 = (uint32_t)rowB0 * 128u + (uint32_t)((kcb ^ (rowB0 & 7)) << 4);
                uint32_t o1 = (uint32_t)rowB1 * 128u + (uint32_t)((kcb ^ (rowB1 & 7)) << 4);
                asm volatile("ldmatrix.sync.aligned.m8n8.x4.shared.b16 {%0,%1,%2,%3}, [%4];"
                             : "=r"(bh[0][0]), "=r"(bh[0][1]), "=r"(bh[1][0]), "=r"(bh[1][1]) : "r"(WH16 + o0));
                asm volatile("ldmatrix.sync.aligned.m8n8.x4.shared.b16 {%0,%1,%2,%3}, [%4];"
                             : "=r"(bh[2][0]), "=r"(bh[2][1]), "=r"(bh[3][0]), "=r"(bh[3][1]) : "r"(WH16 + o1));
            }
            int kca = kk * 2 + (lane >> 4);
            #pragma unroll
            for (int mt = 0; mt < 4; mt++) {
                int rowm = rowmA + mt * 16;
                uint32_t off = (uint32_t)rowm * 128u + (uint32_t)((kca ^ (rowm & 7)) << 4);
                uint32_t ah[4];
                asm volatile("ldmatrix.sync.aligned.m8n8.x4.shared.b16 {%0,%1,%2,%3}, [%4];"
                             : "=r"(ah[0]), "=r"(ah[1]), "=r"(ah[2]), "=r"(ah[3]) : "r"(XH16 + off));
                #pragma unroll
                for (int nt = 0; nt < 4; nt++)
                    MMA16(acc[mt][nt], ah, bh[nt]);
            }
        }

        // ---------- fp8 correction: xh*(wl*2^15) + (xl*2^11)(wh*2^4) ----------
        #pragma unroll
        for (int q = 0; q < 2; q++) {
            uint32_t bwl[4][2], bwh[4][2];
            int cbB = q * 2 + (matB & 1);
            {
                uint32_t o0 = (uint32_t)rowB0 * 64u + (uint32_t)((cbB ^ ((rowB0 >> 1) & 3)) << 4);
                uint32_t o1 = (uint32_t)rowB1 * 64u + (uint32_t)((cbB ^ ((rowB1 >> 1) & 3)) << 4);
                asm volatile("ldmatrix.sync.aligned.m8n8.x4.shared.b16 {%0,%1,%2,%3}, [%4];"
                             : "=r"(bwl[0][0]), "=r"(bwl[0][1]), "=r"(bwl[1][0]), "=r"(bwl[1][1]) : "r"(WL8 + o0));
                asm volatile("ldmatrix.sync.aligned.m8n8.x4.shared.b16 {%0,%1,%2,%3}, [%4];"
                             : "=r"(bwl[2][0]), "=r"(bwl[2][1]), "=r"(bwl[3][0]), "=r"(bwl[3][1]) : "r"(WL8 + o1));
                asm volatile("ldmatrix.sync.aligned.m8n8.x4.shared.b16 {%0,%1,%2,%3}, [%4];"
                             : "=r"(bwh[0][0]), "=r"(bwh[0][1]), "=r"(bwh[1][0]), "=r"(bwh[1][1]) : "r"(WH8 + o0));
                asm volatile("ldmatrix.sync.aligned.m8n8.x4.shared.b16 {%0,%1,%2,%3}, [%4];"
                             : "=r"(bwh[2][0]), "=r"(bwh[2][1]), "=r"(bwh[3][0]), "=r"(bwh[3][1]) : "r"(WH8 + o1));
            }
            int cbA = q * 2 + (lane >> 4);
            #pragma unroll
            for (int mt = 0; mt < 4; mt++) {
                int rowm = rowmA + mt * 16;
                uint32_t off = (uint32_t)rowm * 64u + (uint32_t)((cbA ^ ((rowm >> 1) & 3)) << 4);
                uint32_t axh[4], axl[4];
                asm volatile("ldmatrix.sync.aligned.m8n8.x4.shared.b16 {%0,%1,%2,%3}, [%4];"
                             : "=r"(axh[0]), "=r"(axh[1]), "=r"(axh[2]), "=r"(axh[3]) : "r"(XH8 + off));
                asm volatile("ldmatrix.sync.aligned.m8n8.x4.shared.b16 {%0,%1,%2,%3}, [%4];"
                             : "=r"(axl[0]), "=r"(axl[1]), "=r"(axl[2]), "=r"(axl[3]) : "r"(XL8 + off));
                #pragma unroll
                for (int nt = 0; nt < 4; nt++) {
                    MMA8(acc[mt][nt], axh, bwl[nt]);
                    MMA8(acc[mt][nt], axl, bwh[nt]);
                }
            }
        }
        // trailing __syncthreads elided (3 distinct stages; validated R9/R10)
    }
#undef LOAD_STAGE
#undef STAGE_ADDR
#undef MMA16
#undef MMA8

    // epilogue: z = acc * (inv_s / 2^15) + bias
    float inv_s = s_invs * (1.f / 32768.f);
    int rgrp = lane >> 2, qc = lane & 3;
    #pragma unroll
    for (int mt = 0; mt < 4; mt++) {
        #pragma unroll
        for (int half = 0; half < 2; half++) {
            float sum = 0.f;
            #pragma unroll
            for (int nt = 0; nt < 4; nt++) {
                int f0 = warp_n * 32 + nt * 8 + qc * 2;
                float v0 = acc[mt][nt][half * 2 + 0];
                float v1 = acc[mt][nt][half * 2 + 1];
                float d0 = s_cent[f0]     - fmaf(v0, inv_s, s_bias[f0]);
                float d1 = s_cent[f0 + 1] - fmaf(v1, inv_s, s_bias[f0 + 1]);
                sum = fmaf(d0, d0, sum);
                sum = fmaf(d1, d1, sum);
            }
            sum += __shfl_xor_sync(0xffffffffu, sum, 1);
            sum += __shfl_xor_sync(0xffffffffu, sum, 2);
            if (qc == 0)
                part[warp_m * 64 + mt * 16 + half * 8 + rgrp][warp_n] = sum;
        }
    }
    __syncthreads();
    if (tid < 128) {
        float dist2 = part[tid][0] + part[tid][1] + part[tid][2] + part[tid][3];
        out[(size_t)(bt * 128 + tid) * C_ + c] = expf(-0.5f * dist2);
    }
}

// =====================================================================
// Host
// =====================================================================
extern "C" void kernel_launch(void* const* d_in, const int* in_sizes, int n_in,
                              void* d_out, int out_size)
{
    const float* x = (const float*)d_in[0];   // [512,2048]
    const float* W = (const float*)d_in[1];   // [100,128,2048]
    const float* b = (const float*)d_in[2];   // [100,128]
    const float* u = (const float*)d_in[3];   // [100,128]
    const float* c = (const float*)d_in[4];   // [100,128]
    float* out = (float*)d_out;               // [512,100]

    cudaFuncSetAttribute(mm_kernel, cudaFuncAttributeMaxDynamicSharedMemorySize, DSMEM_SIZE);

    split_x_kernel<<<(B_ * E_) / 512, 256>>>(x);
    wsplit_v_kernel<<<dim3(C_, 2), 256>>>(W, u);
    wv_kernel<<<dim3(C_, 8), 256>>>(W);
    mm_kernel<<<dim3(4, C_), 256, DSMEM_SIZE>>>(b, c, out);
}

// round 15
// speedup vs baseline: 1.1943x; 1.1943x over previous
#include <cuda_runtime.h>
#include <cuda_bf16.h>
#include <cstdint>
#include <cstddef>

#define C_ 100
#define B_ 512
#define E_ 2048
#define F_ 128

#define NKT 64                 // k-tiles of 32
#define STAGE_BYTES 32768      // XH,XL,WH,WL tiles (8KB each)
#define DSMEM_SIZE (3 * STAGE_BYTES)

// ---------------- device scratch ----------------
__device__ __align__(1024) __nv_bfloat16 g_xh[B_ * E_];
__device__ __align__(1024) __nv_bfloat16 g_xl[B_ * E_];
__device__ __align__(1024) __nv_bfloat16 g_wh[(size_t)C_ * F_ * E_];
__device__ __align__(1024) __nv_bfloat16 g_wl[(size_t)C_ * F_ * E_];
__device__ float g_vraw[C_ * E_];
__device__ float g_nrm2p[C_ * 2];
__device__ float g_s2p[C_ * 64];

// ---------------- helpers ----------------
__device__ __forceinline__ uint32_t smem_u32(const void* p) {
    uint32_t a;
    asm("{ .reg .u64 t; cvta.to.shared.u64 t, %1; cvt.u32.u64 %0, t; }" : "=r"(a) : "l"(p));
    return a;
}
__device__ __forceinline__ void cp16(uint32_t dst, const void* src) {
    asm volatile("cp.async.cg.shared.global [%0], [%1], 16;" :: "r"(dst), "l"(src) : "memory");
}

// =====================================================================
// split x into bf16 hi/lo
// =====================================================================
__global__ void split_x_kernel(const float* __restrict__ x) {
    int i = (blockIdx.x * 256 + threadIdx.x) * 2;
    float2 v = *(const float2*)&x[i];
    __nv_bfloat16 h0 = __float2bfloat16(v.x);
    __nv_bfloat16 h1 = __float2bfloat16(v.y);
    __nv_bfloat16 l0 = __float2bfloat16(v.x - __bfloat162float(h0));
    __nv_bfloat16 l1 = __float2bfloat16(v.y - __bfloat162float(h1));
    *(__nv_bfloat162*)&g_xh[i] = __halves2bfloat162(h0, h1);
    *(__nv_bfloat162*)&g_xl[i] = __halves2bfloat162(l0, l1);
}

// =====================================================================
// fused: W -> bf16 hi/lo split AND v_raw = W^T u with partial ||v||^2
// =====================================================================
__global__ void wsplit_v_kernel(const float* __restrict__ W, const float* __restrict__ u) {
    int c = blockIdx.x, et = blockIdx.y;
    __shared__ float su[F_];
    __shared__ float red[8];
    int tid = threadIdx.x, lane = tid & 31, wrp = tid >> 5;

    if (tid < F_) su[tid] = u[c * F_ + tid];
    __syncthreads();

    int e0 = et * 1024 + tid * 4;
    const float* base = W + (size_t)c * F_ * E_ + e0;
    float v0 = 0.f, v1 = 0.f, v2 = 0.f, v3 = 0.f;
    #pragma unroll 8
    for (int f = 0; f < F_; f++) {
        float4 w = *(const float4*)(base + (size_t)f * E_);
        float uf = su[f];
        v0 = fmaf(w.x, uf, v0);
        v1 = fmaf(w.y, uf, v1);
        v2 = fmaf(w.z, uf, v2);
        v3 = fmaf(w.w, uf, v3);
        __nv_bfloat16 h0 = __float2bfloat16(w.x);
        __nv_bfloat16 h1 = __float2bfloat16(w.y);
        __nv_bfloat16 h2 = __float2bfloat16(w.z);
        __nv_bfloat16 h3 = __float2bfloat16(w.w);
        __nv_bfloat16 l0 = __float2bfloat16(w.x - __bfloat162float(h0));
        __nv_bfloat16 l1 = __float2bfloat16(w.y - __bfloat162float(h1));
        __nv_bfloat16 l2 = __float2bfloat16(w.z - __bfloat162float(h2));
        __nv_bfloat16 l3 = __float2bfloat16(w.w - __bfloat162float(h3));
        size_t oi = (size_t)(c * F_ + f) * E_ + e0;
        *(__nv_bfloat162*)&g_wh[oi]     = __halves2bfloat162(h0, h1);
        *(__nv_bfloat162*)&g_wh[oi + 2] = __halves2bfloat162(h2, h3);
        *(__nv_bfloat162*)&g_wl[oi]     = __halves2bfloat162(l0, l1);
        *(__nv_bfloat162*)&g_wl[oi + 2] = __halves2bfloat162(l2, l3);
    }
    *(float4*)&g_vraw[c * E_ + e0] = make_float4(v0, v1, v2, v3);

    float loc = v0 * v0 + v1 * v1 + v2 * v2 + v3 * v3;
    #pragma unroll
    for (int o = 16; o; o >>= 1) loc += __shfl_xor_sync(0xffffffffu, loc, o);
    if (lane == 0) red[wrp] = loc;
    __syncthreads();
    if (tid == 0) {
        float s = 0.f;
        #pragma unroll
        for (int i = 0; i < 8; i++) s += red[i];
        g_nrm2p[c * 2 + et] = s;
    }
}

// =====================================================================
// t = W v_hat; partial sum of t^2. grid (C, 8), 256 threads.
// =====================================================================
__global__ void wv_kernel(const float* __restrict__ W) {
    int c = blockIdx.x, ft = blockIdx.y;
    __shared__ float sv[E_];
    __shared__ float s_inv;
    int tid = threadIdx.x, lane = tid & 31, wrp = tid >> 5;

    if (tid == 0)
        s_inv = 1.f / fmaxf(sqrtf(g_nrm2p[c * 2] + g_nrm2p[c * 2 + 1]), 1e-12f);
    __syncthreads();
    float inv = s_inv;
    for (int i = tid * 4; i < E_; i += 1024) {
        float4 v = *(const float4*)&g_vraw[c * E_ + i];
        v.x *= inv; v.y *= inv; v.z *= inv; v.w *= inv;
        *(float4*)&sv[i] = v;
    }
    __syncthreads();

    int f0 = ft * 16 + wrp * 2;
    const float* p0 = W + ((size_t)c * F_ + f0) * E_;
    const float* p1 = p0 + E_;
    float t0 = 0.f, t1 = 0.f;
    #pragma unroll 8
    for (int e = lane * 4; e < E_; e += 128) {
        float4 a = *(const float4*)(p0 + e);
        float4 b = *(const float4*)(p1 + e);
        float4 v = *(const float4*)&sv[e];
        t0 = fmaf(a.x, v.x, t0); t0 = fmaf(a.y, v.y, t0);
        t0 = fmaf(a.z, v.z, t0); t0 = fmaf(a.w, v.w, t0);
        t1 = fmaf(b.x, v.x, t1); t1 = fmaf(b.y, v.y, t1);
        t1 = fmaf(b.z, v.z, t1); t1 = fmaf(b.w, v.w, t1);
    }
    #pragma unroll
    for (int o = 16; o; o >>= 1) {
        t0 += __shfl_xor_sync(0xffffffffu, t0, o);
        t1 += __shfl_xor_sync(0xffffffffu, t1, o);
    }
    if (lane == 0) g_s2p[c * 64 + ft * 8 + wrp] = t0 * t0 + t1 * t1;
}

// =====================================================================
// Main kernel: FULL 128x128 CTA tile, 64x32 warp tile (as R10), but
// k-tile 32 -> 32KB stages x3 = 96KB -> 2 CTAs/SM co-resident.
// 64-byte smem rows with R11-validated swizzle chunk^((row>>1)&3).
// grid (4, C_).
// =====================================================================
__global__ void __launch_bounds__(256, 2)
mm_kernel(const float* __restrict__ bias, const float* __restrict__ cent,
          float* __restrict__ out)
{
    extern __shared__ __align__(1024) char dsm[];
    __shared__ float s_bias[F_], s_cent[F_];
    __shared__ float part[128][4];
    __shared__ float s_invs;

    int bt = blockIdx.x, c = blockIdx.y;
    int tid = threadIdx.x, wid = tid >> 5, lane = tid & 31;

    if (tid < F_) {
        s_bias[tid] = bias[c * F_ + tid];
        s_cent[tid] = cent[c * F_ + tid];
    }
    if (wid == 0) {
        float s = g_s2p[c * 64 + lane] + g_s2p[c * 64 + 32 + lane];
        #pragma unroll
        for (int o = 16; o; o >>= 1) s += __shfl_xor_sync(0xffffffffu, s, o);
        if (lane == 0) s_invs = 1.f / sqrtf(s);
    }

    uint32_t dbase = smem_u32(dsm);
    int warp_m = wid >> 2, warp_n = wid & 3;   // 2x4 warps, 64x32 tiles

    float acc[4][4][4];
    #pragma unroll
    for (int mt = 0; mt < 4; mt++)
        #pragma unroll
        for (int nt = 0; nt < 4; nt++)
            #pragma unroll
            for (int q = 0; q < 4; q++) acc[mt][nt][q] = 0.f;

    // cp.async mapping: each tile 8KB = 512x16B; 256 threads -> 2/tile
    int r0 = tid >> 1, kc = (tid & 1) * 2;   // row 0..127, chunks {0,1} or {2,3}
    uint32_t dsw0 = (uint32_t)r0 * 64u + (uint32_t)(((kc + 0) ^ ((r0 >> 1) & 3)) << 4);
    uint32_t dsw1 = (uint32_t)r0 * 64u + (uint32_t)(((kc + 1) ^ ((r0 >> 1) & 3)) << 4);

    const __nv_bfloat16* xh_s = g_xh + (size_t)(bt * 128 + r0) * E_ + kc * 8;
    const __nv_bfloat16* xl_s = g_xl + (size_t)(bt * 128 + r0) * E_ + kc * 8;
    const __nv_bfloat16* wh_s = g_wh + (size_t)(c * 128 + r0) * E_ + kc * 8;
    const __nv_bfloat16* wl_s = g_wl + (size_t)(c * 128 + r0) * E_ + kc * 8;

    // fragment addressing
    int matB = lane >> 3, rrB = lane & 7;
    int rowB0 = warp_n * 32 + ((matB >> 1) << 3) + rrB;
    int rowB1 = rowB0 + 16;
    int rowmA = warp_m * 64 + ((lane >> 3) & 1) * 8 + (lane & 7);

#define STAGE_ADDR(s) (dbase + (uint32_t)(s) * (uint32_t)STAGE_BYTES)
#define LOAD_STAGE(slot, kt) do { \
    int _k0 = (kt) << 5; \
    uint32_t _sa = STAGE_ADDR(slot); \
    cp16(_sa + dsw0,           xh_s + _k0); \
    cp16(_sa + dsw1,           xh_s + _k0 + 8); \
    cp16(_sa + 8192u + dsw0,   xl_s + _k0); \
    cp16(_sa + 8192u + dsw1,   xl_s + _k0 + 8); \
    cp16(_sa + 16384u + dsw0,  wh_s + _k0); \
    cp16(_sa + 16384u + dsw1,  wh_s + _k0 + 8); \
    cp16(_sa + 24576u + dsw0,  wl_s + _k0); \
    cp16(_sa + 24576u + dsw1,  wl_s + _k0 + 8); \
    asm volatile("cp.async.commit_group;" ::: "memory"); \
} while (0)

#define MMA(d, a, b) \
    asm volatile("mma.sync.aligned.m16n8k16.row.col.f32.bf16.bf16.f32 " \
                 "{%0,%1,%2,%3}, {%4,%5,%6,%7}, {%8,%9}, {%0,%1,%2,%3};" \
                 : "+f"((d)[0]), "+f"((d)[1]), "+f"((d)[2]), "+f"((d)[3]) \
                 : "r"((a)[0]), "r"((a)[1]), "r"((a)[2]), "r"((a)[3]), \
                   "r"((b)[0]), "r"((b)[1]))

    LOAD_STAGE(0, 0);
    LOAD_STAGE(1, 1);

    for (int it = 0; it < NKT; it++) {
        int s = it % 3;
        if (it == NKT - 1) asm volatile("cp.async.wait_group 0;" ::: "memory");
        else               asm volatile("cp.async.wait_group 1;" ::: "memory");
        __syncthreads();
        if (it + 2 < NKT) LOAD_STAGE((it + 2) % 3, it + 2);

        uint32_t XH = STAGE_ADDR(s);
        uint32_t XL = XH + 8192u;
        uint32_t WH = XH + 16384u;
        uint32_t WL = XH + 24576u;

        #pragma unroll
        for (int kk = 0; kk < 2; kk++) {
            uint32_t bh[4][2], bl[4][2];
            int kcb = kk * 2 + (matB & 1);
            {
                uint32_t o0 = (uint32_t)rowB0 * 64u + (uint32_t)((kcb ^ ((rowB0 >> 1) & 3)) << 4);
                uint32_t o1 = (uint32_t)rowB1 * 64u + (uint32_t)((kcb ^ ((rowB1 >> 1) & 3)) << 4);
                asm volatile("ldmatrix.sync.aligned.m8n8.x4.shared.b16 {%0,%1,%2,%3}, [%4];"
                             : "=r"(bh[0][0]), "=r"(bh[0][1]), "=r"(bh[1][0]), "=r"(bh[1][1]) : "r"(WH + o0));
                asm volatile("ldmatrix.sync.aligned.m8n8.x4.shared.b16 {%0,%1,%2,%3}, [%4];"
                             : "=r"(bl[0][0]), "=r"(bl[0][1]), "=r"(bl[1][0]), "=r"(bl[1][1]) : "r"(WL + o0));
                asm volatile("ldmatrix.sync.aligned.m8n8.x4.shared.b16 {%0,%1,%2,%3}, [%4];"
                             : "=r"(bh[2][0]), "=r"(bh[2][1]), "=r"(bh[3][0]), "=r"(bh[3][1]) : "r"(WH + o1));
                asm volatile("ldmatrix.sync.aligned.m8n8.x4.shared.b16 {%0,%1,%2,%3}, [%4];"
                             : "=r"(bl[2][0]), "=r"(bl[2][1]), "=r"(bl[3][0]), "=r"(bl[3][1]) : "r"(WL + o1));
            }
            int kca = kk * 2 + (lane >> 4);
            #pragma unroll
            for (int mt = 0; mt < 4; mt++) {
                int rowm = rowmA + mt * 16;
                uint32_t off = (uint32_t)rowm * 64u + (uint32_t)((kca ^ ((rowm >> 1) & 3)) << 4);
                uint32_t ah[4], al[4];
                asm volatile("ldmatrix.sync.aligned.m8n8.x4.shared.b16 {%0,%1,%2,%3}, [%4];"
                             : "=r"(ah[0]), "=r"(ah[1]), "=r"(ah[2]), "=r"(ah[3]) : "r"(XH + off));
                asm volatile("ldmatrix.sync.aligned.m8n8.x4.shared.b16 {%0,%1,%2,%3}, [%4];"
                             : "=r"(al[0]), "=r"(al[1]), "=r"(al[2]), "=r"(al[3]) : "r"(XL + off));
                #pragma unroll
                for (int nt = 0; nt < 4; nt++) {
                    MMA(acc[mt][nt], ah, bh[nt]);
                    MMA(acc[mt][nt], ah, bl[nt]);
                    MMA(acc[mt][nt], al, bh[nt]);
                }
            }
        }
        // trailing __syncthreads elided (3 distinct stages; validated R9/R10)
    }
#undef LOAD_STAGE
#undef STAGE_ADDR
#undef MMA

    // epilogue
    float inv_s = s_invs;
    int rgrp = lane >> 2, qc = lane & 3;
    #pragma unroll
    for (int mt = 0; mt < 4; mt++) {
        #pragma unroll
        for (int half = 0; half < 2; half++) {
            float sum = 0.f;
            #pragma unroll
            for (int nt = 0; nt < 4; nt++) {
                int f0 = warp_n * 32 + nt * 8 + qc * 2;
                float v0 = acc[mt][nt][half * 2 + 0];
                float v1 = acc[mt][nt][half * 2 + 1];
                float d0 = s_cent[f0]     - fmaf(v0, inv_s, s_bias[f0]);
                float d1 = s_cent[f0 + 1] - fmaf(v1, inv_s, s_bias[f0 + 1]);
                sum = fmaf(d0, d0, sum);
                sum = fmaf(d1, d1, sum);
            }
            sum += __shfl_xor_sync(0xffffffffu, sum, 1);
            sum += __shfl_xor_sync(0xffffffffu, sum, 2);
            if (qc == 0)
                part[warp_m * 64 + mt * 16 + half * 8 + rgrp][warp_n] = sum;
        }
    }
    __syncthreads();
    if (tid < 128) {
        float dist2 = part[tid][0] + part[tid][1] + part[tid][2] + part[tid][3];
        out[(size_t)(bt * 128 + tid) * C_ + c] = expf(-0.5f * dist2);
    }
}

// =====================================================================
// Host
// =====================================================================
extern "C" void kernel_launch(void* const* d_in, const int* in_sizes, int n_in,
                              void* d_out, int out_size)
{
    const float* x = (const float*)d_in[0];   // [512,2048]
    const float* W = (const float*)d_in[1];   // [100,128,2048]
    const float* b = (const float*)d_in[2];   // [100,128]
    const float* u = (const float*)d_in[3];   // [100,128]
    const float* c = (const float*)d_in[4];   // [100,128]
    float* out = (float*)d_out;               // [512,100]

    cudaFuncSetAttribute(mm_kernel, cudaFuncAttributeMaxDynamicSharedMemorySize, DSMEM_SIZE);

    split_x_kernel<<<(B_ * E_) / 512, 256>>>(x);
    wsplit_v_kernel<<<dim3(C_, 2), 256>>>(W, u);
    wv_kernel<<<dim3(C_, 8), 256>>>(W);
    mm_kernel<<<dim3(4, C_), 256, DSMEM_SIZE>>>(b, c, out);
}

// round 16
// speedup vs baseline: 1.4051x; 1.1765x over previous
#include <cuda_runtime.h>
#include <cuda_bf16.h>
#include <cstdint>
#include <cstddef>

#define C_ 100
#define B_ 512
#define E_ 2048
#define F_ 128

#define NKT 32                 // k-tiles of 64
#define STAGE_BYTES 65536      // XH,XL,WH,WL tiles (16KB each)
#define DSMEM_SIZE (3 * STAGE_BYTES)

// ---------------- device scratch ----------------
__device__ __align__(1024) __nv_bfloat16 g_xh[B_ * E_];
__device__ __align__(1024) __nv_bfloat16 g_xl[B_ * E_];
__device__ __align__(1024) __nv_bfloat16 g_wh[(size_t)C_ * F_ * E_];
__device__ __align__(1024) __nv_bfloat16 g_wl[(size_t)C_ * F_ * E_];
__device__ float g_vraw[C_ * E_];
__device__ float g_nrm2p[C_ * 4];
__device__ float g_s2p[C_ * 64];

// ---------------- helpers ----------------
__device__ __forceinline__ uint32_t smem_u32(const void* p) {
    uint32_t a;
    asm("{ .reg .u64 t; cvta.to.shared.u64 t, %1; cvt.u32.u64 %0, t; }" : "=r"(a) : "l"(p));
    return a;
}
__device__ __forceinline__ void cp16(uint32_t dst, const void* src) {
    asm volatile("cp.async.cg.shared.global [%0], [%1], 16;" :: "r"(dst), "l"(src) : "memory");
}

// =====================================================================
// split x into bf16 hi/lo
// =====================================================================
__global__ void split_x_kernel(const float* __restrict__ x) {
    int i = (blockIdx.x * 256 + threadIdx.x) * 2;
    float2 v = *(const float2*)&x[i];
    __nv_bfloat16 h0 = __float2bfloat16(v.x);
    __nv_bfloat16 h1 = __float2bfloat16(v.y);
    __nv_bfloat16 l0 = __float2bfloat16(v.x - __bfloat162float(h0));
    __nv_bfloat16 l1 = __float2bfloat16(v.y - __bfloat162float(h1));
    *(__nv_bfloat162*)&g_xh[i] = __halves2bfloat162(h0, h1);
    *(__nv_bfloat162*)&g_xl[i] = __halves2bfloat162(l0, l1);
}

// =====================================================================
// fused: W -> bf16 hi/lo split AND v_raw = W^T u with partial ||v||^2
// grid (C, 4), 256 threads; block owns e-range of 512 (2 e per thread)
// =====================================================================
__global__ void wsplit_v_kernel(const float* __restrict__ W, const float* __restrict__ u) {
    int c = blockIdx.x, et = blockIdx.y;
    __shared__ float su[F_];
    __shared__ float red[8];
    int tid = threadIdx.x, lane = tid & 31, wrp = tid >> 5;

    if (tid < F_) su[tid] = u[c * F_ + tid];
    __syncthreads();

    int e0 = et * 512 + tid * 2;
    const float* base = W + (size_t)c * F_ * E_ + e0;
    float v0 = 0.f, v1 = 0.f;
    #pragma unroll 8
    for (int f = 0; f < F_; f++) {
        float2 w = *(const float2*)(base + (size_t)f * E_);
        float uf = su[f];
        v0 = fmaf(w.x, uf, v0);
        v1 = fmaf(w.y, uf, v1);
        __nv_bfloat16 h0 = __float2bfloat16(w.x);
        __nv_bfloat16 h1 = __float2bfloat16(w.y);
        __nv_bfloat16 l0 = __float2bfloat16(w.x - __bfloat162float(h0));
        __nv_bfloat16 l1 = __float2bfloat16(w.y - __bfloat162float(h1));
        size_t oi = (size_t)(c * F_ + f) * E_ + e0;
        *(__nv_bfloat162*)&g_wh[oi] = __halves2bfloat162(h0, h1);
        *(__nv_bfloat162*)&g_wl[oi] = __halves2bfloat162(l0, l1);
    }
    *(float2*)&g_vraw[c * E_ + e0] = make_float2(v0, v1);

    float loc = v0 * v0 + v1 * v1;
    #pragma unroll
    for (int o = 16; o; o >>= 1) loc += __shfl_xor_sync(0xffffffffu, loc, o);
    if (lane == 0) red[wrp] = loc;
    __syncthreads();
    if (tid == 0) {
        float s = 0.f;
        #pragma unroll
        for (int i = 0; i < 8; i++) s += red[i];
        g_nrm2p[c * 4 + et] = s;
    }
}

// =====================================================================
// t = W v_hat; partial sum of t^2. grid (C, 8), 256 threads.
// =====================================================================
__global__ void wv_kernel(const float* __restrict__ W) {
    int c = blockIdx.x, ft = blockIdx.y;
    __shared__ float sv[E_];
    __shared__ float s_inv;
    int tid = threadIdx.x, lane = tid & 31, wrp = tid >> 5;

    if (tid == 0) {
        float n2 = g_nrm2p[c * 4] + g_nrm2p[c * 4 + 1]
                 + g_nrm2p[c * 4 + 2] + g_nrm2p[c * 4 + 3];
        s_inv = 1.f / fmaxf(sqrtf(n2), 1e-12f);
    }
    __syncthreads();
    float inv = s_inv;
    for (int i = tid * 4; i < E_; i += 1024) {
        float4 v = *(const float4*)&g_vraw[c * E_ + i];
        v.x *= inv; v.y *= inv; v.z *= inv; v.w *= inv;
        *(float4*)&sv[i] = v;
    }
    __syncthreads();

    int f0 = ft * 16 + wrp * 2;
    const float* p0 = W + ((size_t)c * F_ + f0) * E_;
    const float* p1 = p0 + E_;
    float t0 = 0.f, t1 = 0.f;
    #pragma unroll 8
    for (int e = lane * 4; e < E_; e += 128) {
        float4 a = *(const float4*)(p0 + e);
        float4 b = *(const float4*)(p1 + e);
        float4 v = *(const float4*)&sv[e];
        t0 = fmaf(a.x, v.x, t0); t0 = fmaf(a.y, v.y, t0);
        t0 = fmaf(a.z, v.z, t0); t0 = fmaf(a.w, v.w, t0);
        t1 = fmaf(b.x, v.x, t1); t1 = fmaf(b.y, v.y, t1);
        t1 = fmaf(b.z, v.z, t1); t1 = fmaf(b.w, v.w, t1);
    }
    #pragma unroll
    for (int o = 16; o; o >>= 1) {
        t0 += __shfl_xor_sync(0xffffffffu, t0, o);
        t1 += __shfl_xor_sync(0xffffffffu, t1, o);
    }
    if (lane == 0) g_s2p[c * 64 + ft * 8 + wrp] = t0 * t0 + t1 * t1;
}

// =====================================================================
// Main kernel (R10 config exactly — the measured mma.sync optimum):
// BM=128, BN=128, fused-term stages (64KB x 3), grid (4, C_).
// =====================================================================
__global__ void __launch_bounds__(256, 1)
mm_kernel(const float* __restrict__ bias, const float* __restrict__ cent,
          float* __restrict__ out)
{
    extern __shared__ __align__(1024) char dsm[];
    __shared__ float s_bias[F_], s_cent[F_];
    __shared__ float part[128][4];
    __shared__ float s_invs;

    int bt = blockIdx.x, c = blockIdx.y;
    int tid = threadIdx.x, wid = tid >> 5, lane = tid & 31;

    if (tid < F_) {
        s_bias[tid] = bias[c * F_ + tid];
        s_cent[tid] = cent[c * F_ + tid];
    }
    if (wid == 0) {
        float s = g_s2p[c * 64 + lane] + g_s2p[c * 64 + 32 + lane];
        #pragma unroll
        for (int o = 16; o; o >>= 1) s += __shfl_xor_sync(0xffffffffu, s, o);
        if (lane == 0) s_invs = 1.f / sqrtf(s);
    }

    uint32_t dbase = smem_u32(dsm);
    int warp_m = wid >> 2, warp_n = wid & 3;

    float acc[4][4][4];
    #pragma unroll
    for (int mt = 0; mt < 4; mt++)
        #pragma unroll
        for (int nt = 0; nt < 4; nt++)
            #pragma unroll
            for (int q = 0; q < 4; q++) acc[mt][nt][q] = 0.f;

    int r0 = tid >> 3, kc = tid & 7;
    uint32_t dcol = (uint32_t)((kc ^ (r0 & 7)) * 16);
    uint32_t drow = (uint32_t)r0 * 128u + dcol;

    const __nv_bfloat16* xh_s = g_xh + (size_t)(bt * 128 + r0) * E_ + kc * 8;
    const __nv_bfloat16* xl_s = g_xl + (size_t)(bt * 128 + r0) * E_ + kc * 8;
    const __nv_bfloat16* wh_s = g_wh + (size_t)(c * 128 + r0) * E_ + kc * 8;
    const __nv_bfloat16* wl_s = g_wl + (size_t)(c * 128 + r0) * E_ + kc * 8;

#define STAGE_ADDR(s) (dbase + (uint32_t)(s) * (uint32_t)STAGE_BYTES)
#define LOAD_STAGE(slot, kt) do { \
    int _k0 = (kt) << 6; \
    uint32_t _da = STAGE_ADDR(slot) + drow; \
    _Pragma("unroll") \
    for (int _j = 0; _j < 4; _j++) { \
        cp16(_da          + _j * 4096u, xh_s + _k0 + (size_t)_j * 32 * E_); \
        cp16(_da + 16384u + _j * 4096u, xl_s + _k0 + (size_t)_j * 32 * E_); \
        cp16(_da + 32768u + _j * 4096u, wh_s + _k0 + (size_t)_j * 32 * E_); \
        cp16(_da + 49152u + _j * 4096u, wl_s + _k0 + (size_t)_j * 32 * E_); \
    } \
    asm volatile("cp.async.commit_group;" ::: "memory"); \
} while (0)

    LOAD_STAGE(0, 0);
    LOAD_STAGE(1, 1);

    for (int it = 0; it < NKT; it++) {
        int s = it % 3;
        if (it == NKT - 1) asm volatile("cp.async.wait_group 0;" ::: "memory");
        else               asm volatile("cp.async.wait_group 1;" ::: "memory");
        __syncthreads();
        if (it + 2 < NKT) LOAD_STAGE((it + 2) % 3, it + 2);

        uint32_t XH = STAGE_ADDR(s);
        uint32_t XL = XH + 16384u;
        uint32_t WH = XH + 32768u;
        uint32_t WL = XH + 49152u;

        #pragma unroll
        for (int kk = 0; kk < 4; kk++) {
            uint32_t bh[4][2], bl[4][2];
            int mat = lane >> 3, rr = lane & 7;
            int kcb = kk * 2 + (mat & 1);
            #pragma unroll
            for (int g = 0; g < 2; g++) {
                int rown = warp_n * 32 + g * 16 + ((mat >> 1) << 3) + rr;
                uint32_t off = (uint32_t)rown * 128u + (uint32_t)((kcb ^ (rown & 7)) << 4);
                uint32_t q0, q1, q2, q3;
                asm volatile("ldmatrix.sync.aligned.m8n8.x4.shared.b16 {%0,%1,%2,%3}, [%4];"
                             : "=r"(q0), "=r"(q1), "=r"(q2), "=r"(q3) : "r"(WH + off));
                bh[g * 2 + 0][0] = q0; bh[g * 2 + 0][1] = q1;
                bh[g * 2 + 1][0] = q2; bh[g * 2 + 1][1] = q3;
                asm volatile("ldmatrix.sync.aligned.m8n8.x4.shared.b16 {%0,%1,%2,%3}, [%4];"
                             : "=r"(q0), "=r"(q1), "=r"(q2), "=r"(q3) : "r"(WL + off));
                bl[g * 2 + 0][0] = q0; bl[g * 2 + 0][1] = q1;
                bl[g * 2 + 1][0] = q2; bl[g * 2 + 1][1] = q3;
            }
            int kca = kk * 2 + (lane >> 4);
            #pragma unroll
            for (int mt = 0; mt < 4; mt++) {
                int rowm = warp_m * 64 + mt * 16 + ((lane >> 3) & 1) * 8 + (lane & 7);
                uint32_t off = (uint32_t)rowm * 128u + (uint32_t)((kca ^ (rowm & 7)) << 4);
                uint32_t a0, a1, a2, a3;
                asm volatile("ldmatrix.sync.aligned.m8n8.x4.shared.b16 {%0,%1,%2,%3}, [%4];"
                             : "=r"(a0), "=r"(a1), "=r"(a2), "=r"(a3) : "r"(XH + off));
                #pragma unroll
                for (int nt = 0; nt < 4; nt++) {
                    asm volatile(
                        "mma.sync.aligned.m16n8k16.row.col.f32.bf16.bf16.f32 "
                        "{%0,%1,%2,%3}, {%4,%5,%6,%7}, {%8,%9}, {%0,%1,%2,%3};"
                        : "+f"(acc[mt][nt][0]), "+f"(acc[mt][nt][1]),
                          "+f"(acc[mt][nt][2]), "+f"(acc[mt][nt][3])
                        : "r"(a0), "r"(a1), "r"(a2), "r"(a3),
                          "r"(bh[nt][0]), "r"(bh[nt][1]));
                    asm volatile(
                        "mma.sync.aligned.m16n8k16.row.col.f32.bf16.bf16.f32 "
                        "{%0,%1,%2,%3}, {%4,%5,%6,%7}, {%8,%9}, {%0,%1,%2,%3};"
                        : "+f"(acc[mt][nt][0]), "+f"(acc[mt][nt][1]),
                          "+f"(acc[mt][nt][2]), "+f"(acc[mt][nt][3])
                        : "r"(a0), "r"(a1), "r"(a2), "r"(a3),
                          "r"(bl[nt][0]), "r"(bl[nt][1]));
                }
                asm volatile("ldmatrix.sync.aligned.m8n8.x4.shared.b16 {%0,%1,%2,%3}, [%4];"
                             : "=r"(a0), "=r"(a1), "=r"(a2), "=r"(a3) : "r"(XL + off));
                #pragma unroll
                for (int nt = 0; nt < 4; nt++) {
                    asm volatile(
                        "mma.sync.aligned.m16n8k16.row.col.f32.bf16.bf16.f32 "
                        "{%0,%1,%2,%3}, {%4,%5,%6,%7}, {%8,%9}, {%0,%1,%2,%3};"
                        : "+f"(acc[mt][nt][0]), "+f"(acc[mt][nt][1]),
                          "+f"(acc[mt][nt][2]), "+f"(acc[mt][nt][3])
                        : "r"(a0), "r"(a1), "r"(a2), "r"(a3),
                          "r"(bh[nt][0]), "r"(bh[nt][1]));
                }
            }
        }
        // trailing __syncthreads elided (3 distinct stages; validated R9/R10)
    }
#undef LOAD_STAGE
#undef STAGE_ADDR

    // epilogue
    float inv_s = s_invs;
    int rgrp = lane >> 2, qc = lane & 3;
    #pragma unroll
    for (int mt = 0; mt < 4; mt++) {
        #pragma unroll
        for (int half = 0; half < 2; half++) {
            float sum = 0.f;
            #pragma unroll
            for (int nt = 0; nt < 4; nt++) {
                int f0 = warp_n * 32 + nt * 8 + qc * 2;
                float v0 = acc[mt][nt][half * 2 + 0];
                float v1 = acc[mt][nt][half * 2 + 1];
                float d0 = s_cent[f0]     - fmaf(v0, inv_s, s_bias[f0]);
                float d1 = s_cent[f0 + 1] - fmaf(v1, inv_s, s_bias[f0 + 1]);
                sum = fmaf(d0, d0, sum);
                sum = fmaf(d1, d1, sum);
            }
            sum += __shfl_xor_sync(0xffffffffu, sum, 1);
            sum += __shfl_xor_sync(0xffffffffu, sum, 2);
            if (qc == 0)
                part[warp_m * 64 + mt * 16 + half * 8 + rgrp][warp_n] = sum;
        }
    }
    __syncthreads();
    if (tid < 128) {
        float dist2 = part[tid][0] + part[tid][1] + part[tid][2] + part[tid][3];
        out[(size_t)(bt * 128 + tid) * C_ + c] = expf(-0.5f * dist2);
    }
}

// =====================================================================
// Host
// =====================================================================
extern "C" void kernel_launch(void* const* d_in, const int* in_sizes, int n_in,
                              void* d_out, int out_size)
{
    const float* x = (const float*)d_in[0];   // [512,2048]
    const float* W = (const float*)d_in[1];   // [100,128,2048]
    const float* b = (const float*)d_in[2];   // [100,128]
    const float* u = (const float*)d_in[3];   // [100,128]
    const float* c = (const float*)d_in[4];   // [100,128]
    float* out = (float*)d_out;               // [512,100]

    cudaFuncSetAttribute(mm_kernel, cudaFuncAttributeMaxDynamicSharedMemorySize, DSMEM_SIZE);

    split_x_kernel<<<(B_ * E_) / 512, 256>>>(x);
    wsplit_v_kernel<<<dim3(C_, 4), 256>>>(W, u);
    wv_kernel<<<dim3(C_, 8), 256>>>(W);
    mm_kernel<<<dim3(4, C_), 256, DSMEM_SIZE>>>(b, c, out);
}